// round 3
// baseline (speedup 1.0000x reference)
#include <cuda_runtime.h>
#include <math.h>

// Problem constants (fixed by the reference).
#define BB 8
#define CC 16
#define NNDIM 512
#define EE 1024
#define POS_PER_B  (NNDIM * NNDIM)        // 262,144
#define GRID_ELEMS (BB * POS_PER_B)       // 2,097,152

// Accumulators (no dynamic allocation allowed).
__device__ double g_sum[BB];
__device__ double g_cnt[BB];

// ---------------------------------------------------------------------------
// 1) Zero the per-batch accumulators (16 doubles — trivial).
// ---------------------------------------------------------------------------
__global__ void init_kernel() {
    int t = threadIdx.x;
    if (t < BB) { g_sum[t] = 0.0; g_cnt[t] = 0.0; }
}

// ---------------------------------------------------------------------------
// 2) Fused main kernel.
//    Base term: every position uses label 0 -> nll0 = log(sum_c exp x_c) - x_0.
//    Blocks 0..BB-1 additionally compute the edge-label correction for batch
//    blockIdx.x:  sum over (deduped, last-write-wins) edges of (x_0 - x_a),
//    restricted to masked-valid cells. These blocks launch first, so their
//    extra O(E^2) shared-memory dedup scan hides under the streaming blocks.
//
//    One thread = 4 consecutive positions (float4 loads; class stride N*N).
// ---------------------------------------------------------------------------
__global__ void __launch_bounds__(256) loss_kernel(
        const float* __restrict__ adj,
        const unsigned char* __restrict__ mask,
        const int* __restrict__ edge_index,
        const int* __restrict__ edge_attr) {
    __shared__ int           s_key[EE];   // (r<<9)|c  — used by blocks < BB
    __shared__ unsigned char s_attr[EE];

    const int t    = threadIdx.x;
    const int idx4 = blockIdx.x * 256 + t;            // float4 index
    const int b    = idx4 >> 16;                      // (idx4*4) >> 18
    const int pos  = (idx4 << 2) & (POS_PER_B - 1);

    const float* base = adj + (size_t)b * CC * POS_PER_B + pos;

    // ---- base log-sum-exp with label 0 ----
    const uchar4 m4 = *reinterpret_cast<const uchar4*>(mask + ((size_t)idx4 << 2));
    const float4 a0 = *reinterpret_cast<const float4*>(base);

    float sx = __expf(a0.x), sy = __expf(a0.y);
    float sz = __expf(a0.z), sw = __expf(a0.w);
    #pragma unroll
    for (int c = 1; c < CC; c++) {
        float4 v = *reinterpret_cast<const float4*>(base + (size_t)c * POS_PER_B);
        sx += __expf(v.x); sy += __expf(v.y);
        sz += __expf(v.z); sw += __expf(v.w);
    }

    float sum = 0.0f, cnt = 0.0f;
    if (m4.x) { sum += __logf(sx) - a0.x; cnt += 1.0f; }
    if (m4.y) { sum += __logf(sy) - a0.y; cnt += 1.0f; }
    if (m4.z) { sum += __logf(sz) - a0.z; cnt += 1.0f; }
    if (m4.w) { sum += __logf(sw) - a0.w; cnt += 1.0f; }

    // ---- edge-label correction (first BB blocks only; cb == this block's b) ----
    if (blockIdx.x < BB) {
        const int cb = blockIdx.x;
        const int2* ei = reinterpret_cast<const int2*>(edge_index)
                       + (size_t)cb * EE;
        for (int e = t; e < EE; e += 256) {
            const int2 rc = ei[e];
            s_key[e]  = (rc.x << 9) | rc.y;
            s_attr[e] = (unsigned char)edge_attr[cb * EE + e];
        }
        __syncthreads();
        float corr = 0.0f;
        for (int e = t; e < EE; e += 256) {
            const int key = s_key[e];
            const int a   = s_attr[e];
            bool live = true;                 // last write wins among duplicates
            for (int j = e + 1; j < EE; j++) {
                if (s_key[j] == key) { live = false; break; }
            }
            if (live && a != 0) {
                const int r = key >> 9, c = key & (NNDIM - 1);
                const size_t cell = (size_t)cb * POS_PER_B + (size_t)r * NNDIM + c;
                if (mask[cell]) {
                    const float* p = adj + (size_t)cb * CC * POS_PER_B
                                   + (size_t)r * NNDIM + c;
                    corr += p[0] - p[(size_t)a * POS_PER_B];  // swap x_0 -> x_a
                }
            }
        }
        sum += corr;
    }

    // ---- block reduction ----
    #pragma unroll
    for (int off = 16; off > 0; off >>= 1) {
        sum += __shfl_down_sync(0xFFFFFFFFu, sum, off);
        cnt += __shfl_down_sync(0xFFFFFFFFu, cnt, off);
    }
    __shared__ float r_sum[8];
    __shared__ float r_cnt[8];
    const int lane = t & 31, warp = t >> 5;
    if (lane == 0) { r_sum[warp] = sum; r_cnt[warp] = cnt; }
    __syncthreads();
    if (warp == 0) {
        float bs = (lane < 8) ? r_sum[lane] : 0.0f;
        float bc = (lane < 8) ? r_cnt[lane] : 0.0f;
        #pragma unroll
        for (int off = 4; off > 0; off >>= 1) {
            bs += __shfl_down_sync(0xFFFFFFFFu, bs, off);
            bc += __shfl_down_sync(0xFFFFFFFFu, bc, off);
        }
        if (lane == 0) {
            // Each block lies entirely inside one batch b.
            atomicAdd(&g_sum[b], (double)bs);
            atomicAdd(&g_cnt[b], (double)bc);
        }
    }
}

// ---------------------------------------------------------------------------
// 3) Finalize in parallel: lane b computes sum_b / max(cnt_b, 1); shuffle
//    reduce; lane 0 writes the batch mean.
// ---------------------------------------------------------------------------
__global__ void final_kernel(float* __restrict__ out) {
    const int lane = threadIdx.x;
    double v = 0.0;
    if (lane < BB) {
        double c = g_cnt[lane];
        if (c < 1.0) c = 1.0;
        v = g_sum[lane] / c;
    }
    #pragma unroll
    for (int off = 4; off > 0; off >>= 1)
        v += __shfl_down_sync(0xFFFFFFFFu, v, off);
    if (lane == 0) out[0] = (float)(v / (double)BB);
}

// ---------------------------------------------------------------------------
// kernel_launch — inputs (metadata order): adj f32 [B,C,N,N], mask bool(u8)
// [B,N,N], edge_index i32 [B,E,2], edge_attr i32 [B,E]. Output: 1 fp32 scalar.
// ---------------------------------------------------------------------------
extern "C" void kernel_launch(void* const* d_in, const int* in_sizes, int n_in,
                              void* d_out, int out_size) {
    const float*         adj        = (const float*)d_in[0];
    const unsigned char* mask       = (const unsigned char*)d_in[1];
    const int*           edge_index = (const int*)d_in[2];
    const int*           edge_attr  = (const int*)d_in[3];
    float*               out        = (float*)d_out;

    init_kernel<<<1, 32>>>();
    loss_kernel<<<GRID_ELEMS / 4 / 256, 256>>>(adj, mask, edge_index, edge_attr);
    final_kernel<<<1, 32>>>(out);
}

// round 4
// speedup vs baseline: 2.8280x; 2.8280x over previous
#include <cuda_runtime.h>
#include <math.h>

// Problem constants (fixed by the reference).
#define BB 8
#define CC 16
#define NNDIM 512
#define EE 1024
#define POS_PER_B  (NNDIM * NNDIM)        // 262,144
#define GRID_ELEMS (BB * POS_PER_B)       // 2,097,152
#define NBLK (GRID_ELEMS / 4 / 256)       // 2048 loss blocks
#define HASH_SZ 4096

// Accumulators (no dynamic allocation allowed).
__device__ double g_sum[BB];
__device__ double g_cnt[BB];
__device__ unsigned int g_done;

// ---------------------------------------------------------------------------
// 1) Correction kernel: one block per batch, one thread per edge.
//    - Zeroes per-batch accumulators (and the ticket counter).
//    - Exact last-write-wins dedup of edges via an O(E) shared hash table
//      (atomicCAS claims a slot per cell key; atomicMax keeps the highest
//      edge index = last scatter write, matching the CPU reference).
//    - For each live edge with attr != 0 at a masked-valid cell, accumulates
//      (x_class0 - x_attr): the base loss (computed with label 0 everywhere
//      by the streaming kernel) is corrected to the true label.
// ---------------------------------------------------------------------------
__global__ void __launch_bounds__(EE) corr_kernel(
        const float* __restrict__ adj,
        const unsigned char* __restrict__ mask,
        const int* __restrict__ edge_index,
        const int* __restrict__ edge_attr) {
    __shared__ int s_slotkey[HASH_SZ];
    __shared__ int s_slotval[HASH_SZ];
    const int b = blockIdx.x;
    const int e = threadIdx.x;               // 0..EE-1

    if (e == 0) {
        g_sum[b] = 0.0;
        g_cnt[b] = 0.0;
        if (b == 0) g_done = 0u;
    }
    #pragma unroll
    for (int i = e; i < HASH_SZ; i += EE) {
        s_slotkey[i] = -1;
        s_slotval[i] = -1;
    }

    const int2 rc  = reinterpret_cast<const int2*>(edge_index)[(size_t)b * EE + e];
    const int key  = (rc.x << 9) | rc.y;     // r, c in [0, 512)
    const int attr = edge_attr[b * EE + e];
    __syncthreads();

    // Insert: claim slot for key (linear probing), record max edge index.
    unsigned h = (((unsigned)key * 2654435761u) >> 20) & (HASH_SZ - 1);
    while (true) {
        int old = atomicCAS(&s_slotkey[h], -1, key);
        if (old == -1 || old == key) { atomicMax(&s_slotval[h], e); break; }
        h = (h + 1) & (HASH_SZ - 1);
    }
    __syncthreads();

    // h now points at this key's slot; this edge is live iff it is the last.
    const bool live = (s_slotval[h] == e);

    float corr = 0.0f;
    if (live && attr != 0) {
        const size_t cell = (size_t)b * POS_PER_B + (size_t)rc.x * NNDIM + rc.y;
        if (mask[cell]) {
            const float* p = adj + (size_t)b * CC * POS_PER_B
                           + (size_t)rc.x * NNDIM + rc.y;
            corr = p[0] - p[(size_t)attr * POS_PER_B];   // swap x_0 -> x_attr
        }
    }

    // Block reduction (32 warps).
    #pragma unroll
    for (int off = 16; off > 0; off >>= 1)
        corr += __shfl_down_sync(0xFFFFFFFFu, corr, off);
    __shared__ float r_sum[32];
    const int lane = e & 31, warp = e >> 5;
    if (lane == 0) r_sum[warp] = corr;
    __syncthreads();
    if (warp == 0) {
        float v = r_sum[lane];
        #pragma unroll
        for (int off = 16; off > 0; off >>= 1)
            v += __shfl_down_sync(0xFFFFFFFFu, v, off);
        if (lane == 0) atomicAdd(&g_sum[b], (double)v);
    }
}

// ---------------------------------------------------------------------------
// 2) Streaming loss kernel: one thread = 4 consecutive positions.
//    nll0 = log(sum_c exp x_c) - x_0 at every masked-valid position.
//    Last block (ticket pattern) computes the final batch-mean scalar.
// ---------------------------------------------------------------------------
__global__ void __launch_bounds__(256) loss_kernel(
        const float* __restrict__ adj,
        const unsigned char* __restrict__ mask,
        float* __restrict__ out) {
    const int t    = threadIdx.x;
    const int idx4 = blockIdx.x * 256 + t;            // float4 index
    const int b    = idx4 >> 16;                      // 65536 float4 per batch
    const int pos  = (idx4 << 2) & (POS_PER_B - 1);

    const float* base = adj + (size_t)b * CC * POS_PER_B + pos;

    const uchar4 m4 = *reinterpret_cast<const uchar4*>(mask + ((size_t)idx4 << 2));
    const float4 a0 = *reinterpret_cast<const float4*>(base);

    float sx = __expf(a0.x), sy = __expf(a0.y);
    float sz = __expf(a0.z), sw = __expf(a0.w);
    #pragma unroll
    for (int c = 1; c < CC; c++) {
        float4 v = *reinterpret_cast<const float4*>(base + (size_t)c * POS_PER_B);
        sx += __expf(v.x); sy += __expf(v.y);
        sz += __expf(v.z); sw += __expf(v.w);
    }

    float sum = 0.0f, cnt = 0.0f;
    if (m4.x) { sum += __logf(sx) - a0.x; cnt += 1.0f; }
    if (m4.y) { sum += __logf(sy) - a0.y; cnt += 1.0f; }
    if (m4.z) { sum += __logf(sz) - a0.z; cnt += 1.0f; }
    if (m4.w) { sum += __logf(sw) - a0.w; cnt += 1.0f; }

    // Block reduction (8 warps).
    #pragma unroll
    for (int off = 16; off > 0; off >>= 1) {
        sum += __shfl_down_sync(0xFFFFFFFFu, sum, off);
        cnt += __shfl_down_sync(0xFFFFFFFFu, cnt, off);
    }
    __shared__ float r_sum[8];
    __shared__ float r_cnt[8];
    const int lane = t & 31, warp = t >> 5;
    if (lane == 0) { r_sum[warp] = sum; r_cnt[warp] = cnt; }
    __syncthreads();

    if (warp == 0 && lane == 0) {
        float bs = 0.0f, bc = 0.0f;
        #pragma unroll
        for (int w = 0; w < 8; w++) { bs += r_sum[w]; bc += r_cnt[w]; }
        // Each block lies entirely inside one batch b.
        atomicAdd(&g_sum[b], (double)bs);
        atomicAdd(&g_cnt[b], (double)bc);

        __threadfence();
        const unsigned ticket = atomicAdd(&g_done, 1u);
        if (ticket == NBLK - 1) {
            // All other blocks' atomics are visible (fence-before-ticket).
            double acc = 0.0;
            #pragma unroll
            for (int i = 0; i < BB; i++) {
                volatile double* vs = g_sum;
                volatile double* vc = g_cnt;
                double c = vc[i];
                if (c < 1.0) c = 1.0;
                acc += vs[i] / c;
            }
            out[0] = (float)(acc / (double)BB);
        }
    }
}

// ---------------------------------------------------------------------------
// kernel_launch — inputs (metadata order): adj f32 [B,C,N,N], mask bool(u8)
// [B,N,N], edge_index i32 [B,E,2], edge_attr i32 [B,E]. Output: 1 fp32 scalar.
// ---------------------------------------------------------------------------
extern "C" void kernel_launch(void* const* d_in, const int* in_sizes, int n_in,
                              void* d_out, int out_size) {
    const float*         adj        = (const float*)d_in[0];
    const unsigned char* mask       = (const unsigned char*)d_in[1];
    const int*           edge_index = (const int*)d_in[2];
    const int*           edge_attr  = (const int*)d_in[3];
    float*               out        = (float*)d_out;

    corr_kernel<<<BB, EE>>>(adj, mask, edge_index, edge_attr);
    loss_kernel<<<NBLK, 256>>>(adj, mask, out);
}